// round 4
// baseline (speedup 1.0000x reference)
#include <cuda_runtime.h>
#include <cuda_bf16.h>
#include <cstdint>

#define N_NODES 50000
#define N_EDGES 1600000
#define FEAT    48
#define NUM_RELS 8

// ---------------------------------------------------------------------------
// Scratch: h2[n][r][48] (76.8 MB) — __device__ global, no allocations.
// ---------------------------------------------------------------------------
__device__ float g_h2[(size_t)N_NODES * NUM_RELS * FEAT];
__device__ int   g_src_is64;

// ---------------------------------------------------------------------------
// Packed f32x2 helpers (Blackwell sm_103a) — ptxas never auto-fuses these.
// ---------------------------------------------------------------------------
__device__ __forceinline__ unsigned long long pack2(float lo, float hi) {
    unsigned long long r;
    asm("mov.b64 %0, {%1, %2};" : "=l"(r) : "f"(lo), "f"(hi));
    return r;
}
__device__ __forceinline__ void unpack2(float& lo, float& hi, unsigned long long v) {
    asm("mov.b64 {%0, %1}, %2;" : "=f"(lo), "=f"(hi) : "l"(v));
}
#define FMA2(d, a, b) \
    asm("fma.rn.f32x2 %0, %1, %2, %0;" : "+l"(d) : "l"(a), "l"(b))

#define RED4(p, a, b, c, d) \
    asm volatile("red.global.add.v4.f32 [%0], {%1, %2, %3, %4};" \
                 :: "l"(p), "f"(a), "f"(b), "f"(c), "f"(d) : "memory")

// ---------------------------------------------------------------------------
// K_detect: is src int64 (hi words all zero) or int32?
// Values are in [0, 50000): for int32 data the odd 32-bit words are random
// node ids — 256 of them all being zero has probability ~ (2e-5)^256 ≈ 0.
// ---------------------------------------------------------------------------
__global__ void detect_kernel(const int* __restrict__ src) {
    __shared__ int s_any;
    if (threadIdx.x == 0) s_any = 0;
    __syncthreads();
    unsigned v = (unsigned)src[2 * threadIdx.x + 1];
    unsigned any = __ballot_sync(0xFFFFFFFFu, v != 0u);
    if ((threadIdx.x & 31) == 0 && any) atomicOr(&s_any, 1);
    __syncthreads();
    if (threadIdx.x == 0) g_src_is64 = (s_any == 0) ? 1 : 0;
}

// ---------------------------------------------------------------------------
// K1: fused per-(node, rel) MLP:
//   h1 = relu(x @ W1[r] + b1); h2 = h1 @ W2[r]  -> g_h2[n][r][:]
// Block: 256 threads = 256 nodes, one relation (blockIdx.y).
// Weights in smem, broadcast LDS.128; accumulators packed f32x2.
// ---------------------------------------------------------------------------
__global__ __launch_bounds__(256, 2)
void rgcn_gemm_kernel(const float* __restrict__ X,
                      const float* __restrict__ W1,
                      const float* __restrict__ W2,
                      const float* __restrict__ b1) {
    __shared__ __align__(16) float W1s[FEAT * FEAT];
    __shared__ __align__(16) float W2s[FEAT * FEAT];
    __shared__ float b1s[FEAT];

    const int r = blockIdx.y;
    const int tid = threadIdx.x;

    // cooperative weight load (coalesced)
    const float* w1g = W1 + (size_t)r * FEAT * FEAT;
    const float* w2g = W2 + (size_t)r * FEAT * FEAT;
    for (int k = tid; k < FEAT * FEAT; k += 256) {
        W1s[k] = w1g[k];
        W2s[k] = w2g[k];
    }
    if (tid < FEAT) b1s[tid] = b1[tid];
    __syncthreads();

    const int n = blockIdx.x * 256 + tid;
    if (n >= N_NODES) return;

    // ---- stage 1: h1 = relu(x @ W1 + b1) ----
    unsigned long long acc[FEAT / 2];
#pragma unroll
    for (int k = 0; k < FEAT / 2; k++) acc[k] = pack2(b1s[2 * k], b1s[2 * k + 1]);

    const float4* x4 = reinterpret_cast<const float4*>(X + (size_t)n * FEAT);
#pragma unroll
    for (int i4 = 0; i4 < FEAT / 4; i4++) {
        float4 xv = x4[i4];
        float xs0 = xv.x, xs1 = xv.y, xs2 = xv.z, xs3 = xv.w;
#pragma unroll
        for (int u = 0; u < 4; u++) {
            float xi = (u == 0) ? xs0 : (u == 1) ? xs1 : (u == 2) ? xs2 : xs3;
            unsigned long long xi2 = pack2(xi, xi);
            const ulonglong2* w =
                reinterpret_cast<const ulonglong2*>(W1s + (i4 * 4 + u) * FEAT);
#pragma unroll
            for (int k = 0; k < FEAT / 4; k++) {
                ulonglong2 wv = w[k];
                FMA2(acc[2 * k],     xi2, wv.x);
                FMA2(acc[2 * k + 1], xi2, wv.y);
            }
        }
    }

    float h1[FEAT];
#pragma unroll
    for (int k = 0; k < FEAT / 2; k++) {
        float lo, hi;
        unpack2(lo, hi, acc[k]);
        h1[2 * k]     = fmaxf(lo, 0.0f);
        h1[2 * k + 1] = fmaxf(hi, 0.0f);
    }

    // ---- stage 2: h2 = h1 @ W2 ----
    unsigned long long acc2[FEAT / 2];
#pragma unroll
    for (int k = 0; k < FEAT / 2; k++) acc2[k] = 0ull;

#pragma unroll
    for (int j = 0; j < FEAT; j++) {
        unsigned long long hj2 = pack2(h1[j], h1[j]);
        const ulonglong2* w = reinterpret_cast<const ulonglong2*>(W2s + j * FEAT);
#pragma unroll
        for (int k = 0; k < FEAT / 4; k++) {
            ulonglong2 wv = w[k];
            FMA2(acc2[2 * k],     hj2, wv.x);
            FMA2(acc2[2 * k + 1], hj2, wv.y);
        }
    }

    // store h2 row (16B-aligned: ((n*8+r)*48*4) % 16 == 0)
    ulonglong2* orow = reinterpret_cast<ulonglong2*>(
        g_h2 + ((size_t)n * NUM_RELS + r) * FEAT);
#pragma unroll
    for (int k = 0; k < FEAT / 4; k++) {
        ulonglong2 o;
        o.x = acc2[2 * k];
        o.y = acc2[2 * k + 1];
        orow[k] = o;
    }
}

// ---------------------------------------------------------------------------
// K2: per-edge gather h2[src,rel] * norm, vector-reduce-add into out[dst].
// ---------------------------------------------------------------------------
__global__ __launch_bounds__(256)
void edge_kernel(const int* __restrict__ src,
                 const int* __restrict__ dst,
                 const int* __restrict__ rel,
                 const float* __restrict__ norm,
                 float* __restrict__ out) {
    const int e = blockIdx.x * 256 + threadIdx.x;
    if (e >= N_EDGES) return;

    const int is64 = g_src_is64;
    const int s = is64 ? src[2 * e] : src[e];
    const int d = dst[e];
    const int r = rel[e];
    const float nm = norm[e];

    const float4* row = reinterpret_cast<const float4*>(
        g_h2 + ((size_t)s * NUM_RELS + r) * FEAT);
    float* orow = out + (size_t)d * FEAT;

#pragma unroll
    for (int k = 0; k < FEAT / 4; k++) {
        float4 v = row[k];
        RED4(orow + 4 * k, v.x * nm, v.y * nm, v.z * nm, v.w * nm);
    }
}

// ---------------------------------------------------------------------------
// K3: out = relu(agg + bias2), vectorized float4, in place.
// ---------------------------------------------------------------------------
__global__ __launch_bounds__(256)
void finalize_kernel(float* __restrict__ out, const float* __restrict__ b2) {
    const int total4 = N_NODES * (FEAT / 4);
    int i = blockIdx.x * 256 + threadIdx.x;
    if (i >= total4) return;
    const float4* b4 = reinterpret_cast<const float4*>(b2);
    float4 bb = b4[i % (FEAT / 4)];
    float4 v = reinterpret_cast<float4*>(out)[i];
    v.x = fmaxf(v.x + bb.x, 0.0f);
    v.y = fmaxf(v.y + bb.y, 0.0f);
    v.z = fmaxf(v.z + bb.z, 0.0f);
    v.w = fmaxf(v.w + bb.w, 0.0f);
    reinterpret_cast<float4*>(out)[i] = v;
}

// ---------------------------------------------------------------------------
// launch
// ---------------------------------------------------------------------------
extern "C" void kernel_launch(void* const* d_in, const int* in_sizes, int n_in,
                              void* d_out, int out_size) {
    const float* X    = (const float*)d_in[0];
    const float* norm = (const float*)d_in[1];
    const float* W1   = (const float*)d_in[2];
    const float* W2   = (const float*)d_in[3];
    const float* b1   = (const float*)d_in[4];
    const float* b2   = (const float*)d_in[5];
    const int*   src  = (const int*)d_in[6];   // int32 or int64 (detected)
    const int*   dst  = (const int*)d_in[7];
    const int*   rel  = (const int*)d_in[8];
    float* out = (float*)d_out;

    (void)in_sizes; (void)n_in;

    // zero the accumulation target (d_out is poisoned by the harness)
    cudaMemsetAsync(out, 0, (size_t)out_size * sizeof(float), 0);

    // src dtype detection (tiny, once per replay)
    detect_kernel<<<1, 256>>>(src);

    // fused dense stage -> g_h2
    dim3 g1((N_NODES + 255) / 256, NUM_RELS);
    rgcn_gemm_kernel<<<g1, 256>>>(X, W1, W2, b1);

    // edge gather + vector reduce-add
    edge_kernel<<<(N_EDGES + 255) / 256, 256>>>(src, dst, rel, norm, out);

    // bias + relu
    finalize_kernel<<<(N_NODES * (FEAT / 4) + 255) / 256, 256>>>(out, b2);
}